// round 10
// baseline (speedup 1.0000x reference)
#include <cuda_runtime.h>
#include <cstddef>

#define NB 128
#define HS 33  // h row stride in float2 (odd -> conflict-free 4-row access)

__device__ float g_xp[(size_t)512 * 64 * 4096];  // [t][b][pcol]
__device__ float g_wxh[512 * 4096];              // [k][pcol], pcol=j*4+gate
__device__ float g_whh[1024 * 4096];
__device__ float g_bias[4096];
__device__ float g_h[2][64 * 1024];
__device__ unsigned g_cnt;

__device__ __forceinline__ void ffma2(unsigned long long &a, unsigned long long x,
                                      unsigned long long y) {
    asm volatile("fma.rn.f32x2 %0, %1, %2, %0;" : "+l"(a) : "l"(x), "l"(y));
}
__device__ __forceinline__ unsigned long long pk(float x, float y) {
    unsigned long long r;
    asm("mov.b64 %0,{%1,%2};" : "=l"(r) : "f"(x), "f"(y));
    return r;
}
__device__ __forceinline__ void upk(unsigned long long v, float &x, float &y) {
    asm("mov.b64 {%0,%1},%2;" : "=f"(x), "=f"(y) : "l"(v));
}
__device__ __forceinline__ float sigm(float x) { return 1.f / (1.f + expf(-x)); }

// ---------------- pack: permute weights to pcol = j*4+gate; reset state ----------------
__global__ void pack_kernel(const float *__restrict__ wxh, const float *__restrict__ whh,
                            const float *__restrict__ bias) {
    int stride = gridDim.x * blockDim.x;
    int i0 = blockIdx.x * blockDim.x + threadIdx.x;
    for (int idx = i0; idx < 1024 * 4096; idx += stride) {
        int k = idx >> 12, pcol = idx & 4095;
        int src = ((pcol & 3) << 10) + (pcol >> 2);  // gate*1024 + j
        g_whh[idx] = whh[(size_t)k * 4096 + src];
        if (k < 512) g_wxh[idx] = wxh[(size_t)k * 4096 + src];
        if (k == 0) g_bias[pcol] = bias[src];
    }
    for (int idx = i0; idx < 2 * 64 * 1024; idx += stride) (&g_h[0][0])[idx] = 0.f;
    if (i0 == 0) g_cnt = 0u;
}

// ---------------- projection: g_xp[t][b][:] = X[b,t,:] @ Wp + bias ----------------
// M=32768 (m=b*512+t), N=4096, K=512. Tile 64x128, 256 thr, micro 4x8 (f32x2 col pairs).
__global__ void __launch_bounds__(256, 2) proj_kernel(const float *__restrict__ X) {
    __shared__ float As[2][16][66];
    __shared__ float Bs[2][16][132];
    int tid = threadIdx.x;
    int tx = tid & 15, ty = tid >> 4;
    int n0 = blockIdx.x * 128, m0 = blockIdx.y * 64;

    unsigned long long acc[4][4];
#pragma unroll
    for (int i = 0; i < 4; ++i)
#pragma unroll
        for (int q = 0; q < 4; ++q) acc[i][q] = 0ull;

    int am = tid >> 2, ak = (tid & 3) << 2;   // A loader: row am, 4 k's
    int bk = tid >> 5, bc = (tid & 31) << 2;  // B loader: 2 rows (bk, bk+8), 4 cols

    float4 Av, Bv0, Bv1;
    Av = *(const float4 *)(X + (size_t)(m0 + am) * 512 + ak);
    Bv0 = *(const float4 *)(g_wxh + (size_t)bk * 4096 + n0 + bc);
    Bv1 = *(const float4 *)(g_wxh + (size_t)(bk + 8) * 4096 + n0 + bc);
    As[0][ak + 0][am] = Av.x; As[0][ak + 1][am] = Av.y;
    As[0][ak + 2][am] = Av.z; As[0][ak + 3][am] = Av.w;
    *(float4 *)&Bs[0][bk][bc] = Bv0;
    *(float4 *)&Bs[0][bk + 8][bc] = Bv1;
    __syncthreads();

    for (int kt = 0; kt < 32; ++kt) {
        int cur = kt & 1;
        if (kt < 31) {
            int kb = (kt + 1) << 4;
            Av = *(const float4 *)(X + (size_t)(m0 + am) * 512 + kb + ak);
            Bv0 = *(const float4 *)(g_wxh + (size_t)(kb + bk) * 4096 + n0 + bc);
            Bv1 = *(const float4 *)(g_wxh + (size_t)(kb + bk + 8) * 4096 + n0 + bc);
        }
#pragma unroll
        for (int k = 0; k < 16; ++k) {
            unsigned long long a[4], b[4];
#pragma unroll
            for (int i = 0; i < 4; ++i) {
                float av = As[cur][k][(ty << 2) + i];
                a[i] = pk(av, av);
            }
#pragma unroll
            for (int q = 0; q < 4; ++q)
                b[q] = *(const unsigned long long *)&Bs[cur][k][2 * tx + 32 * q];
#pragma unroll
            for (int i = 0; i < 4; ++i)
#pragma unroll
                for (int q = 0; q < 4; ++q) ffma2(acc[i][q], a[i], b[q]);
        }
        if (kt < 31) {
            int nb = cur ^ 1;
            As[nb][ak + 0][am] = Av.x; As[nb][ak + 1][am] = Av.y;
            As[nb][ak + 2][am] = Av.z; As[nb][ak + 3][am] = Av.w;
            *(float4 *)&Bs[nb][bk][bc] = Bv0;
            *(float4 *)&Bs[nb][bk + 8][bc] = Bv1;
        }
        __syncthreads();
    }

    float2 bb[4];
#pragma unroll
    for (int q = 0; q < 4; ++q) bb[q] = *(const float2 *)&g_bias[n0 + 2 * tx + 32 * q];
#pragma unroll
    for (int i = 0; i < 4; ++i) {
        int m = m0 + (ty << 2) + i;
        int t = m & 511, b = m >> 9;
        size_t base = ((size_t)t * 64 + b) * 4096 + n0 + 2 * tx;
#pragma unroll
        for (int q = 0; q < 4; ++q) {
            float lo, hi;
            upk(acc[i][q], lo, hi);
            float2 v = make_float2(lo + bb[q].x, hi + bb[q].y);
            *(float2 *)&g_xp[base + 32 * q] = v;
        }
    }
}

// ---------------- persistent recurrence: 128 blocks x 128 threads ----------------
// Block p owns j in [8p,8p+8). Thread (rg,jp): rows 4rg..4rg+3, one j (4 gates).
// W slice in SMEM all steps (layout [kp][g][jp], K-paired); h double-buffered chunks.
__global__ void __launch_bounds__(128, 1)
recur_kernel(const float *__restrict__ scale, const float *__restrict__ offs,
             const float *__restrict__ mean, const float *__restrict__ var,
             float *__restrict__ out) {
    extern __shared__ float2 sm[];
    float2 *sW = sm;           // 512 kp * 32 = 16384 float2 (128 KB)
    float2 *sH = sm + 16384;   // 2 * 64 * HS float2

    int tid = threadIdx.x, p = blockIdx.x;
    int jp = tid & 7, rg = tid >> 3;  // rg 0..15
    int j = (p << 3) + jp;

    // load W_HH slice, pack K pairs: sW[kp*32 + g*8 + jp] = (w[2kp], w[2kp+1])
    for (int it = 0; it < 128; ++it) {
        int idx = tid + (it << 7);
        int kp = idx >> 5, lc = idx & 31;
        int g = lc & 3, jj = lc >> 2;
        float w0 = g_whh[(size_t)(2 * kp) * 4096 + (p << 5) + lc];
        float w1 = g_whh[(size_t)(2 * kp + 1) * 4096 + (p << 5) + lc];
        sW[(kp << 5) + (g << 3) + jj] = make_float2(w0, w1);
    }
    float c[4] = {0.f, 0.f, 0.f, 0.f};
    __syncthreads();

    for (int t = 0; t < 512; ++t) {
        const float *hsrc = g_h[t & 1];
        float *hdst = g_h[(t + 1) & 1];
        float mu = __ldg(mean + t * 1024 + j);
        float iss = __ldg(scale + t * 1024 + j) * rsqrtf(__ldg(var + t * 1024 + j) + 1e-5f);
        float off = __ldg(offs + t * 1024 + j);

        unsigned long long acc[4][4];
#pragma unroll
        for (int i = 0; i < 4; ++i) {
            const float4 x = *(const float4 *)&g_xp[((size_t)t * 64 + (rg << 2) + i) * 4096 +
                                                    (p << 5) + (jp << 2)];
            acc[i][0] = pk(x.x, 0.f); acc[i][1] = pk(x.y, 0.f);
            acc[i][2] = pk(x.z, 0.f); acc[i][3] = pk(x.w, 0.f);
        }

        float4 pf[8];
#pragma unroll
        for (int ii = 0; ii < 8; ++ii) {
            int lin = tid + (ii << 7);
            pf[ii] = __ldcg((const float4 *)&hsrc[(lin >> 4) * 1024 + ((lin & 15) << 2)]);
        }
        int cur = 0;
        for (int ch = 0; ch < 16; ++ch) {
#pragma unroll
            for (int ii = 0; ii < 8; ++ii) {
                int lin = tid + (ii << 7);
                float2 *d = &sH[cur * 64 * HS + (lin >> 4) * HS + ((lin & 15) << 1)];
                d[0] = make_float2(pf[ii].x, pf[ii].y);
                d[1] = make_float2(pf[ii].z, pf[ii].w);
            }
            __syncthreads();
            if (ch < 15) {
                int kb = (ch + 1) << 6;
#pragma unroll
                for (int ii = 0; ii < 8; ++ii) {
                    int lin = tid + (ii << 7);
                    pf[ii] = __ldcg(
                        (const float4 *)&hsrc[(lin >> 4) * 1024 + kb + ((lin & 15) << 2)]);
                }
            }
            const float2 *wb = sW + (ch << 10) + jp;  // ch*32 kpairs * 32
            const float2 *hb = sH + cur * 64 * HS;
#pragma unroll 8
            for (int kk = 0; kk < 32; ++kk) {
                unsigned long long w0 = *(const unsigned long long *)&wb[(kk << 5)];
                unsigned long long w1 = *(const unsigned long long *)&wb[(kk << 5) + 8];
                unsigned long long w2 = *(const unsigned long long *)&wb[(kk << 5) + 16];
                unsigned long long w3 = *(const unsigned long long *)&wb[(kk << 5) + 24];
#pragma unroll
                for (int i = 0; i < 4; ++i) {
                    unsigned long long hv =
                        *(const unsigned long long *)&hb[((rg << 2) + i) * HS + kk];
                    ffma2(acc[i][0], hv, w0);
                    ffma2(acc[i][1], hv, w1);
                    ffma2(acc[i][2], hv, w2);
                    ffma2(acc[i][3], hv, w3);
                }
            }
            cur ^= 1;
        }

#pragma unroll
        for (int i = 0; i < 4; ++i) {
            float s[4];
#pragma unroll
            for (int g = 0; g < 4; ++g) {
                float lo, hi;
                upk(acc[i][g], lo, hi);
                s[g] = lo + hi;
            }
            // gate order: f, i, o, gbar
            c[i] = sigm(s[0] + 1.f) * c[i] + sigm(s[1]) * tanhf(s[3]);
            float cn = (c[i] - mu) * iss + off;
            float h = sigm(s[2]) * tanhf(cn);
            hdst[((rg << 2) + i) * 1024 + j] = h;
            if (t == 511) out[((rg << 2) + i) * 1024 + j] = h;
        }

        // grid barrier (release/acquire, monotonic counter)
        __syncthreads();
        if (tid == 0) {
            asm volatile("red.release.gpu.add.u32 [%0], %1;" ::"l"(&g_cnt), "r"(1u)
                         : "memory");
            unsigned target = (unsigned)(t + 1) * NB, x;
            do {
                asm volatile("ld.acquire.gpu.u32 %0, [%1];" : "=r"(x) : "l"(&g_cnt) : "memory");
            } while (x < target);
        }
        __syncthreads();
    }
}

extern "C" void kernel_launch(void *const *d_in, const int *in_sizes, int n_in, void *d_out,
                              int out_size) {
    const float *X = (const float *)d_in[0];
    const float *wxh = (const float *)d_in[1];
    const float *whh = (const float *)d_in[2];
    const float *bias = (const float *)d_in[3];
    const float *scale = (const float *)d_in[4];
    const float *offs = (const float *)d_in[5];
    const float *mean = (const float *)d_in[6];
    const float *var = (const float *)d_in[7];

    int smem = (16384 + 2 * 64 * HS) * (int)sizeof(float2);  // 164,864 B
    cudaFuncSetAttribute(recur_kernel, cudaFuncAttributeMaxDynamicSharedMemorySize, smem);

    pack_kernel<<<256, 256>>>(wxh, whh, bias);
    proj_kernel<<<dim3(32, 512), 256>>>(X);
    recur_kernel<<<NB, 128, smem>>>(scale, offs, mean, var, (float *)d_out);
}